// round 16
// baseline (speedup 1.0000x reference)
#include <cuda_runtime.h>
#include <math.h>

#define BATCH 8
#define CH    256
#define NPIX  4096
#define LOG2E 1.4426950408889634f

// ---------------- scratch ----------------
__device__ float g_qbuf[BATCH * NPIX * 32];           // [b][n][d]  fp32 Q
__device__ float g_kbuf[BATCH * NPIX * 32];           // [b][n][d]  tf32 K
__device__ float g_vbuf[BATCH * CH * NPIX];           // [b][c][n]  tf32 V
__device__ float g_inp[BATCH * 2 * CH];
__device__ float g_ax[BATCH * CH];

// ---------------- helpers ----------------
__device__ __forceinline__ unsigned f2tf(float x) {
    unsigned u;
    asm("cvt.rna.tf32.f32 %0, %1;" : "=r"(u) : "f"(x));
    return u;
}
__device__ __forceinline__ float f2tff(float x) {
    return __uint_as_float(f2tf(x));
}
__device__ __forceinline__ float ex2f(float x) {
    float r;
    asm("ex2.approx.f32 %0, %1;" : "=f"(r) : "f"(x));
    return r;
}
__device__ __forceinline__ void mma_tf32(float* c, const unsigned* a, unsigned b0, unsigned b1) {
    asm volatile("mma.sync.aligned.m16n8k8.row.col.f32.tf32.tf32.f32 "
                 "{%0,%1,%2,%3}, {%4,%5,%6,%7}, {%8,%9}, {%0,%1,%2,%3};"
                 : "+f"(c[0]), "+f"(c[1]), "+f"(c[2]), "+f"(c[3])
                 : "r"(a[0]), "r"(a[1]), "r"(a[2]), "r"(a[3]), "r"(b0), "r"(b1));
}
__device__ __forceinline__ void ldsm4(unsigned& r0, unsigned& r1, unsigned& r2, unsigned& r3,
                                      unsigned addr) {
    asm volatile("ldmatrix.sync.aligned.m8n8.x4.shared.b16 {%0,%1,%2,%3}, [%4];"
                 : "=r"(r0), "=r"(r1), "=r"(r2), "=r"(r3) : "r"(addr));
}
__device__ __forceinline__ void cpa16(unsigned dst, const void* src) {
    asm volatile("cp.async.cg.shared.global [%0], [%1], 16;" :: "r"(dst), "l"(src));
}
__device__ __forceinline__ void cpa_commit() {
    asm volatile("cp.async.commit_group;" ::: "memory");
}
__device__ __forceinline__ void cpa_wait1() {
    asm volatile("cp.async.wait_group 1;" ::: "memory");
}
__device__ __forceinline__ void cpa_wait_all() {
    asm volatile("cp.async.wait_group 0;" ::: "memory");
}

// ---------------- kernel 1: per-(b,c) mean / unbiased std ----------------
__global__ void stats_kernel(const float* __restrict__ x) {
    int bc = blockIdx.x;
    const float4* row = (const float4*)(x + (size_t)bc * NPIX);
    float s = 0.f, ss = 0.f;
    for (int i = threadIdx.x; i < NPIX / 4; i += 256) {
        float4 v = row[i];
        s  += v.x + v.y + v.z + v.w;
        ss += v.x * v.x + v.y * v.y + v.z * v.z + v.w * v.w;
    }
    __shared__ float rs[8], rss[8];
    unsigned fm = 0xffffffffu;
    for (int o = 16; o > 0; o >>= 1) {
        s  += __shfl_down_sync(fm, s, o);
        ss += __shfl_down_sync(fm, ss, o);
    }
    int w = threadIdx.x >> 5, l = threadIdx.x & 31;
    if (l == 0) { rs[w] = s; rss[w] = ss; }
    __syncthreads();
    if (threadIdx.x == 0) {
        float S = 0.f, SS = 0.f;
        for (int i = 0; i < 8; i++) { S += rs[i]; SS += rss[i]; }
        float mean = S / (float)NPIX;
        float var  = fmaxf((SS - S * mean) / (float)(NPIX - 1), 0.f);
        int b = bc >> 8, c = bc & 255;
        g_inp[b * 512 + c]       = mean;
        g_inp[b * 512 + 256 + c] = sqrtf(var);
    }
}

// ---------------- kernel 2: SE gate MLP ----------------
__global__ void gate_kernel(const float* __restrict__ W1, const float* __restrict__ W2,
                            const float* __restrict__ lamb) {
    int b = blockIdx.x;
    int tid = threadIdx.x;
    __shared__ float inps[512];
    __shared__ float hs[32];
    for (int i = tid; i < 512; i += 256) inps[i] = g_inp[b * 512 + i];
    __syncthreads();
    if (tid < 32) {
        const float* w = W1 + tid * 512;
        float a = 0.f;
        for (int j = 0; j < 512; j++) a = fmaf(inps[j], w[j], a);
        hs[tid] = fmaxf(a, 0.f);
    }
    __syncthreads();
    const float* w2 = W2 + tid * 32;
    float a = 0.f;
#pragma unroll
    for (int r = 0; r < 32; r++) a = fmaf(hs[r], w2[r], a);
    float sig = 1.f / (1.f + __expf(-a));
    g_ax[b * 256 + tid] = lamb[0] * sig + 1.f;
}

// ---------------- kernel 3: q/k/v projection via tf32 mma (unchanged) ----------------
__global__ __launch_bounds__(256) void proj_kernel(
    const float* __restrict__ x,
    const float* __restrict__ Wq, const float* __restrict__ bq,
    const float* __restrict__ Wk, const float* __restrict__ bk,
    const float* __restrict__ Wv, const float* __restrict__ bv) {
    __shared__ float smp[8448];
    float* Ws = smp;
    float* Xs = smp + 2304;
    const int tid  = threadIdx.x;
    const int n0   = blockIdx.x * 128;
    const int r0   = blockIdx.y * 64;
    const int b    = blockIdx.z;
    const int wid  = tid >> 5;
    const int lane = tid & 31;
    const int g    = lane >> 2;
    const int t    = lane & 3;
    const int mm   = lane >> 3;
    const int lrow = lane & 7;
    const int wr   = wid & 1;
    const int wn2  = wid >> 1;
    const unsigned smb = (unsigned)__cvta_generic_to_shared(smp);

    const unsigned aB = smb + ((wr * 32 + (mm >> 1) * 8 + lrow) * 36) * 4 + (mm & 1) * 16;
    const unsigned bB = smb + (2304 + (wn2 * 32 + (mm >> 1) * 8 + lrow) * 36) * 4 + (mm & 1) * 16;

    float cacc[2][4][4];
#pragma unroll
    for (int i = 0; i < 2; i++)
#pragma unroll
        for (int j = 0; j < 4; j++)
#pragma unroll
            for (int r = 0; r < 4; r++) cacc[i][j][r] = 0.f;

    const int cblk = tid >> 5;
    const int nblk = tid & 31;

    for (int c0 = 0; c0 < 256; c0 += 32) {
        __syncthreads();
#pragma unroll
        for (int k2 = 0; k2 < 2; k2++) {
            int idx = tid + k2 * 256;
            int r = idx >> 3, c4 = idx & 7;
            int rg = r0 + r;
            const float* wsrc = (rg < 32) ? (Wq + rg * 256)
                              : (rg < 64) ? (Wk + (rg - 32) * 256)
                                          : (Wv + (rg - 64) * 256);
            float4 wv = *(const float4*)(wsrc + c0 + c4 * 4);
            float4 hv;
            hv.x = f2tff(wv.x); hv.y = f2tff(wv.y);
            hv.z = f2tff(wv.z); hv.w = f2tff(wv.w);
            *(float4*)&Ws[r * 36 + c4 * 4] = hv;
        }
        {
            float4 xr[4];
#pragma unroll
            for (int j = 0; j < 4; j++)
                xr[j] = *(const float4*)(x + (size_t)(b * 256 + c0 + cblk * 4 + j) * NPIX
                                           + n0 + nblk * 4);
            const float* xf = (const float*)xr;
#pragma unroll
            for (int i = 0; i < 4; i++) {
                float4 tv;
                tv.x = f2tff(xf[i]);
                tv.y = f2tff(xf[4 + i]);
                tv.z = f2tff(xf[8 + i]);
                tv.w = f2tff(xf[12 + i]);
                *(float4*)&Xs[(nblk * 4 + i) * 36 + cblk * 4] = tv;
            }
        }
        __syncthreads();
#pragma unroll
        for (int k8 = 0; k8 < 4; k8++) {
            unsigned af[2][4], bf[2][4];
#pragma unroll
            for (int mf = 0; mf < 2; mf++) {
                unsigned r0r, r1r, r2r, r3r;
                ldsm4(r0r, r1r, r2r, r3r, aB + mf * (16 * 36 * 4) + k8 * 32);
                af[mf][0] = r0r; af[mf][1] = r2r; af[mf][2] = r1r; af[mf][3] = r3r;
            }
#pragma unroll
            for (int nh = 0; nh < 2; nh++)
                ldsm4(bf[nh][0], bf[nh][1], bf[nh][2], bf[nh][3],
                      bB + nh * (16 * 36 * 4) + k8 * 32);
#pragma unroll
            for (int mf = 0; mf < 2; mf++) {
                mma_tf32(cacc[mf][0], af[mf], bf[0][0], bf[0][1]);
                mma_tf32(cacc[mf][1], af[mf], bf[0][2], bf[0][3]);
                mma_tf32(cacc[mf][2], af[mf], bf[1][0], bf[1][1]);
                mma_tf32(cacc[mf][3], af[mf], bf[1][2], bf[1][3]);
            }
        }
    }

#pragma unroll
    for (int mf = 0; mf < 2; mf++) {
        int rlo = wr * 32 + mf * 16 + g;
        int rhi = rlo + 8;
        float blo, bhi;
        if (r0 == 0) {
            blo = (rlo < 32) ? bq[rlo] : bk[rlo - 32];
            bhi = (rhi < 32) ? bq[rhi] : bk[rhi - 32];
        } else {
            blo = bv[r0 - 64 + rlo];
            bhi = bv[r0 - 64 + rhi];
        }
#pragma unroll
        for (int nf = 0; nf < 4; nf++) {
            cacc[mf][nf][0] += blo; cacc[mf][nf][1] += blo;
            cacc[mf][nf][2] += bhi; cacc[mf][nf][3] += bhi;
        }
    }

    if (r0 == 0) {
        __syncthreads();
#pragma unroll
        for (int mf = 0; mf < 2; mf++) {
            int rlo = wr * 32 + mf * 16 + g;
#pragma unroll
            for (int nf = 0; nf < 4; nf++) {
                int n = wn2 * 32 + nf * 8 + 2 * t;
                *(float2*)&smp[rlo * 132 + n]       = make_float2(cacc[mf][nf][0], cacc[mf][nf][1]);
                *(float2*)&smp[(rlo + 8) * 132 + n] = make_float2(cacc[mf][nf][2], cacc[mf][nf][3]);
            }
        }
        __syncthreads();
        float* qdst = g_qbuf + ((size_t)b * NPIX + n0) * 32;
        float* kdst = g_kbuf + ((size_t)b * NPIX + n0) * 32;
#pragma unroll
        for (int k2 = 0; k2 < 4; k2++) {
            int idx = tid + k2 * 256;
            int n = idx >> 3, c4 = idx & 7;
            float4 v;
            v.x = smp[(c4 * 4 + 0) * 132 + n];
            v.y = smp[(c4 * 4 + 1) * 132 + n];
            v.z = smp[(c4 * 4 + 2) * 132 + n];
            v.w = smp[(c4 * 4 + 3) * 132 + n];
            *(float4*)&qdst[n * 32 + c4 * 4] = v;
        }
#pragma unroll
        for (int k2 = 0; k2 < 4; k2++) {
            int idx = tid + k2 * 256;
            int n = idx >> 3, c4 = idx & 7;
            float4 v;
            v.x = f2tff(smp[(32 + c4 * 4 + 0) * 132 + n]);
            v.y = f2tff(smp[(32 + c4 * 4 + 1) * 132 + n]);
            v.z = f2tff(smp[(32 + c4 * 4 + 2) * 132 + n]);
            v.w = f2tff(smp[(32 + c4 * 4 + 3) * 132 + n]);
            *(float4*)&kdst[n * 32 + c4 * 4] = v;
        }
    } else {
        float* vdst = g_vbuf + (size_t)b * CH * NPIX;
#pragma unroll
        for (int mf = 0; mf < 2; mf++) {
            int rlo = wr * 32 + mf * 16 + g;
#pragma unroll
            for (int nf = 0; nf < 4; nf++) {
                int n = n0 + wn2 * 32 + nf * 8 + 2 * t;
                *(float2*)(vdst + (size_t)(r0 - 64 + rlo) * NPIX + n) =
                    make_float2(f2tff(cacc[mf][nf][0]), f2tff(cacc[mf][nf][1]));
                *(float2*)(vdst + (size_t)(r0 - 64 + rlo + 8) * NPIX + n) =
                    make_float2(f2tff(cacc[mf][nf][2]), f2tff(cacc[mf][nf][3]));
            }
        }
    }
}

// ---------------- kernel 4: skewed-pipeline flash attention ----------------
// Body of iter it fuses S[it+1] (K single buffer -> PS[nxt]) with PV[it] (PS[cur], V[it]).
// PS ping-pong; V refill warp-local; K refilled after the end barrier.
// Barriers/iter: 2, but S and PV now share one region -> tensor/crossbar overlap.
#define SM_V    0            // [256 c][64 n] swizzled  16384 fl
#define SM_K    16384        // [64 n][36] K (single)    2304 fl
#define SM_PS0  18688        // [64 m][68] P buf0        4352 fl
#define SM_PS1  23040        // [64 m][68] P buf1        4352 fl
#define SM_PSUM 27392        // [2][64] final l halves
#define SM_TOT  27520        // -> 110080 B (2 CTA/SM)
#define SM_T    0            // epilogue transpose [256][68] (17408 fl < SM_PS0)

__global__ __launch_bounds__(256, 2) void flash_kernel(
    const float* __restrict__ x, const float* __restrict__ gamma,
    float* __restrict__ out) {
    extern __shared__ float sm[];
    const unsigned smb = (unsigned)__cvta_generic_to_shared(sm);
    const int tid  = threadIdx.x;
    const int b    = blockIdx.y;
    const int m0   = blockIdx.x * 64;
    const int wid  = tid >> 5;
    const int lane = tid & 31;
    const int g    = lane >> 2;
    const int t    = lane & 3;
    const int wm   = wid >> 1;
    const int wn   = wid & 1;
    const int mm   = lane >> 3;
    const int lrow = lane & 7;

    const float* qb = g_qbuf + (size_t)b * NPIX * 32;
    const float* kb = g_kbuf + (size_t)b * NPIX * 32;
    const float* vb = g_vbuf + (size_t)b * CH * NPIX;

    // ---- preload Q fragments, pre-scaled by log2(e) ----
    unsigned qh[4][4];
    {
        int r0g = m0 + wm * 16 + g;
#pragma unroll
        for (int q = 0; q < 4; q++) {
            qh[q][0] = f2tf(qb[r0g * 32 + q * 8 + t] * LOG2E);
            qh[q][1] = f2tf(qb[(r0g + 8) * 32 + q * 8 + t] * LOG2E);
            qh[q][2] = f2tf(qb[r0g * 32 + q * 8 + t + 4] * LOG2E);
            qh[q][3] = f2tf(qb[(r0g + 8) * 32 + q * 8 + t + 4] * LOG2E);
        }
    }

    const int  krow = wn * 32 + (mm >> 1) * 8 + lrow;
    const unsigned kbase = smb + (SM_K + krow * 36) * 4 + (mm & 1) * 16;
    const int  c0 = wid * 32;
    const unsigned vB  = smb + SM_V * 4 + (c0 + (mm >> 1) * 8 + lrow) * 256;
    const int  vx  = lrow;
    const int  cu0 = mm & 1;
    // PV read base inside a PS buffer (add buffer offset per iter): rows (mm&1)*8+lrow, unit (mm>>1)
    const unsigned psRB = smb + (((mm & 1) * 8 + lrow) * 68) * 4 + ((mm >> 1) << 4);

    float oacc[4][4][4];
#pragma unroll
    for (int i = 0; i < 4; i++)
#pragma unroll
        for (int j = 0; j < 4; j++)
#pragma unroll
            for (int r = 0; r < 4; r++) oacc[i][j][r] = 0.f;

    float lrun0 = 0.f, lrun1 = 0.f;
    const int ml0 = wm * 16 + g, ml1 = ml0 + 8;

    // ---- preloop: issue {K0}, {V0}; wait K0; S[0] -> PS0; then issue {K1} ----
    {
#pragma unroll
        for (int k = 0; k < 2; k++) {
            int idx = tid + k * 256;
            int row = idx >> 3, c4 = idx & 7;
            cpa16(smb + (SM_K + row * 36 + c4 * 4) * 4, kb + (size_t)row * 32 + c4 * 4);
        }
        cpa_commit();
#pragma unroll
        for (int k = 0; k < 16; k++) {
            int idx = tid + k * 256;
            int c = idx >> 4, u = idx & 15;
            cpa16(smb + SM_V * 4 + c * 256 + ((u ^ (c & 7)) << 4),
                  vb + (size_t)c * NPIX + u * 4);
        }
        cpa_commit();
        cpa_wait1();                           // K0 done (V0 still in flight)
        __syncthreads();

        // S[0] -> PS0
        float sacc[4][4];
#pragma unroll
        for (int j = 0; j < 4; j++)
#pragma unroll
            for (int r = 0; r < 4; r++) sacc[j][r] = 0.f;
#pragma unroll
        for (int q = 0; q < 4; q++) {
#pragma unroll
            for (int jp = 0; jp < 2; jp++) {
                unsigned bh[4];
                ldsm4(bh[0], bh[1], bh[2], bh[3], kbase + jp * 2304 + q * 32);
                mma_tf32(sacc[2 * jp],     qh[q], bh[0], bh[1]);
                mma_tf32(sacc[2 * jp + 1], qh[q], bh[2], bh[3]);
            }
        }
#pragma unroll
        for (int j = 0; j < 4; j++) {
            float p0 = ex2f(sacc[j][0]);
            float p1 = ex2f(sacc[j][1]);
            float p2 = ex2f(sacc[j][2]);
            float p3 = ex2f(sacc[j][3]);
            lrun0 += p0 + p1;
            lrun1 += p2 + p3;
            int col = wn * 32 + j * 8 + 2 * t;
            *(float2*)&sm[SM_PS0 + ml0 * 68 + col] = make_float2(p0, p1);
            *(float2*)&sm[SM_PS0 + ml1 * 68 + col] = make_float2(p2, p3);
        }
        __syncthreads();                       // all S[0] K-reads + PS0 writes done
        // issue K1 into the (now free) single K buffer
#pragma unroll
        for (int k = 0; k < 2; k++) {
            int idx = tid + k * 256;
            int row = idx >> 3, c4 = idx & 7;
            cpa16(smb + (SM_K + row * 36 + c4 * 4) * 4, kb + (size_t)(64 + row) * 32 + c4 * 4);
        }
        cpa_commit();
    }

    for (int it = 0; it < 64; it++) {
        cpa_wait_all();                        // V[it] and K[it+1] complete
        __syncthreads();                       // visibility + PS swap point

        const unsigned psW = (unsigned)(((it + 1) & 1) ? SM_PS1 : SM_PS0);
        const unsigned psR = psRB + (((it & 1) ? SM_PS1 : SM_PS0)) * 4;

        // ---- S[it+1] (fused with PV below; same barrier region) ----
        float sacc[4][4];
        if (it < 63) {
#pragma unroll
            for (int j = 0; j < 4; j++)
#pragma unroll
                for (int r = 0; r < 4; r++) sacc[j][r] = 0.f;
#pragma unroll
            for (int q = 0; q < 4; q++) {
#pragma unroll
                for (int jp = 0; jp < 2; jp++) {
                    unsigned bh[4];
                    ldsm4(bh[0], bh[1], bh[2], bh[3], kbase + jp * 2304 + q * 32);
                    mma_tf32(sacc[2 * jp],     qh[q], bh[0], bh[1]);
                    mma_tf32(sacc[2 * jp + 1], qh[q], bh[2], bh[3]);
                }
            }
#pragma unroll
            for (int j = 0; j < 4; j++) {
                float p0 = ex2f(sacc[j][0]);
                float p1 = ex2f(sacc[j][1]);
                float p2 = ex2f(sacc[j][2]);
                float p3 = ex2f(sacc[j][3]);
                lrun0 += p0 + p1;
                lrun1 += p2 + p3;
                int col = wn * 32 + j * 8 + 2 * t;
                *(float2*)&sm[psW + ml0 * 68 + col] = make_float2(p0, p1);
                *(float2*)&sm[psW + ml1 * 68 + col] = make_float2(p2, p3);
            }
        }

        // ---- PV[it]: PS[cur] x V[it] ----
#pragma unroll
        for (int kk = 0; kk < 8; kk++) {
            unsigned pa[4][4];
#pragma unroll
            for (int i = 0; i < 4; i++)
                ldsm4(pa[i][0], pa[i][1], pa[i][2], pa[i][3], psR + i * 4352 + kk * 32);
            const unsigned ucol = (unsigned)(((kk * 2 + cu0) ^ vx) << 4);
#pragma unroll
            for (int u = 0; u < 2; u++) {
                unsigned vf[4];
                ldsm4(vf[0], vf[1], vf[2], vf[3], vB + u * 4096 + ucol);
#pragma unroll
                for (int i = 0; i < 4; i++) {
                    mma_tf32(oacc[i][u * 2],     pa[i], vf[0], vf[1]);
                    mma_tf32(oacc[i][u * 2 + 1], pa[i], vf[2], vf[3]);
                }
            }
        }
        __syncthreads();                       // end barrier: S[it+1]+PV[it] done everywhere

        // ---- fills: {K[it+2]} (single buffer now free), {V[it+1] warp-local} ----
        if (it < 62) {
            const int n2 = (it + 2) * 64;
#pragma unroll
            for (int k = 0; k < 2; k++) {
                int idx = tid + k * 256;
                int row = idx >> 3, c4 = idx & 7;
                cpa16(smb + (SM_K + row * 36 + c4 * 4) * 4,
                      kb + (size_t)(n2 + row) * 32 + c4 * 4);
            }
        }
        cpa_commit();
        if (it < 63) {
            const int n1 = (it + 1) * 64;
#pragma unroll
            for (int k = 0; k < 16; k++) {
                int idx = lane + k * 32;       // warp-local: own c-slice only
                int c = c0 + (idx >> 4), u = idx & 15;
                cpa16(smb + SM_V * 4 + c * 256 + ((u ^ (c & 7)) << 4),
                      vb + (size_t)c * NPIX + n1 + u * 4);
            }
        }
        cpa_commit();
    }

    // ---- final l reduction ----
    lrun0 += __shfl_xor_sync(0xffffffffu, lrun0, 1);
    lrun0 += __shfl_xor_sync(0xffffffffu, lrun0, 2);
    lrun1 += __shfl_xor_sync(0xffffffffu, lrun1, 1);
    lrun1 += __shfl_xor_sync(0xffffffffu, lrun1, 2);
    if (t == 0) {
        sm[SM_PSUM + wn * 64 + ml0] = lrun0;
        sm[SM_PSUM + wn * 64 + ml1] = lrun1;
    }
    cpa_wait_all();
    __syncthreads();
    float inv[8];
#pragma unroll
    for (int i = 0; i < 4; i++) {
        int rlo = i * 16 + g, rhi = rlo + 8;
        inv[2 * i]     = 1.f / (sm[SM_PSUM + rlo] + sm[SM_PSUM + 64 + rlo]);
        inv[2 * i + 1] = 1.f / (sm[SM_PSUM + rhi] + sm[SM_PSUM + 64 + rhi]);
    }
    __syncthreads();
#pragma unroll
    for (int i = 0; i < 4; i++)
#pragma unroll
        for (int j = 0; j < 4; j++) {
            int c = c0 + j * 8 + 2 * t;
            sm[SM_T + c * 68 + i * 16 + g]           = oacc[i][j][0] * inv[2 * i];
            sm[SM_T + (c + 1) * 68 + i * 16 + g]     = oacc[i][j][1] * inv[2 * i];
            sm[SM_T + c * 68 + i * 16 + 8 + g]       = oacc[i][j][2] * inv[2 * i + 1];
            sm[SM_T + (c + 1) * 68 + i * 16 + 8 + g] = oacc[i][j][3] * inv[2 * i + 1];
        }
    __syncthreads();
    float gval = *gamma;
    const float* xb = x   + (size_t)b * CH * NPIX + m0;
    float*       ob = out + (size_t)b * CH * NPIX + m0;
#pragma unroll
    for (int k = 0; k < 16; k++) {
        int idx = tid + k * 256;
        int c = idx >> 4, m4 = (idx & 15) * 4;
        float4 o  = *(const float4*)&sm[SM_T + c * 68 + m4];
        float4 xv = *(const float4*)(xb + (size_t)c * NPIX + m4);
        float ax = g_ax[b * 256 + c];
        float4 r;
        r.x = fmaf(gval, o.x, ax * xv.x);
        r.y = fmaf(gval, o.y, ax * xv.y);
        r.z = fmaf(gval, o.z, ax * xv.z);
        r.w = fmaf(gval, o.w, ax * xv.w);
        *(float4*)(ob + (size_t)c * NPIX + m4) = r;
    }
}

// ---------------- launch ----------------
extern "C" void kernel_launch(void* const* d_in, const int* in_sizes, int n_in,
                              void* d_out, int out_size) {
    const float* x     = (const float*)d_in[0];
    const float* Wq    = (const float*)d_in[1];
    const float* bq    = (const float*)d_in[2];
    const float* Wk    = (const float*)d_in[3];
    const float* bk    = (const float*)d_in[4];
    const float* Wv    = (const float*)d_in[5];
    const float* bv    = (const float*)d_in[6];
    const float* gamma = (const float*)d_in[7];
    const float* W1    = (const float*)d_in[8];
    const float* W2    = (const float*)d_in[9];
    const float* lamb  = (const float*)d_in[10];
    float* out = (float*)d_out;

    cudaFuncSetAttribute(flash_kernel, cudaFuncAttributeMaxDynamicSharedMemorySize, SM_TOT * 4);

    stats_kernel<<<BATCH * CH, 256>>>(x);
    gate_kernel<<<BATCH, 256>>>(W1, W2, lamb);
    proj_kernel<<<dim3(32, 5, 8), 256>>>(x, Wq, bq, Wk, bk, Wv, bv);
    flash_kernel<<<dim3(64, 8), 256, SM_TOT * 4>>>(x, gamma, out);
}